// round 7
// baseline (speedup 1.0000x reference)
#include <cuda_runtime.h>

// VQ-VAE quantizer, round 6: token-pair x code-pair f32x2 register tiling.
//   h:          (256,512,32) f32  -> 131072 tokens x 32
//   embeddings: (1024,32)    f32
// out (f32): quantized_st (131072*32) | indices (131072) | loss (131072)
//
// Exactness: identical fp32 expression tree to the passing R5 kernel
// (sumsq32 lane-reduction for norms, single ascending-k FMA chain per dot,
// dist = fl(fl(a+b) - 2*dot), strict-< ascending-index argmin). f32x2 ops
// are per-lane IEEE fp32 RN == scalar.
//
// Perf: was L1-bound (80.7%) at 1 token of reuse per smem load. Now each
// loaded code-pair u64 feeds 4 tokens (2 token-pair packed registers + one
// lane-swapped copy) -> 4x less LDS, FFMA2 pipe becomes the bound.

#define DIM    32
#define NCODES 1024
#define NPAIR  (NCODES / 2)       // 512
#define TPB    256
#define NTOK   131072
#define TPT    4                  // tokens per thread
#define NBLK   (NTOK / (TPB * TPT))  // 128

typedef unsigned long long u64;

__device__ __forceinline__ u64 pk2(float lo, float hi) {
    u64 r;
    asm("mov.b64 %0, {%1, %2};" : "=l"(r) : "f"(lo), "f"(hi));
    return r;
}
__device__ __forceinline__ void upk2(u64 v, float& lo, float& hi) {
    asm("mov.b64 {%0, %1}, %2;" : "=f"(lo), "=f"(hi) : "l"(v));
}
__device__ __forceinline__ u64 swp2(u64 v) {   // swap the two f32 lanes
    float lo, hi;
    upk2(v, lo, hi);
    return pk2(hi, lo);
}
// Packed fp32 FMA / ADD — per-lane IEEE RN, bit-identical to scalar.
__device__ __forceinline__ u64 ffma2(u64 a, u64 b, u64 c) {
    u64 d;
    asm("fma.rn.f32x2 %0, %1, %2, %3;" : "=l"(d) : "l"(a), "l"(b), "l"(c));
    return d;
}
__device__ __forceinline__ u64 fadd2(u64 a, u64 b) {
    u64 d;
    asm("add.rn.f32x2 %0, %1, %2;" : "=l"(d) : "l"(a), "l"(b));
    return d;
}

// ||x||^2, XLA-CPU-style 4-lane reduction then (A0+A1)+(A2+A3).
__device__ __forceinline__ float sumsq32(const float* x) {
    float A0 = __fmul_rn(x[0], x[0]);
    float A1 = __fmul_rn(x[1], x[1]);
    float A2 = __fmul_rn(x[2], x[2]);
    float A3 = __fmul_rn(x[3], x[3]);
#pragma unroll
    for (int i = 1; i < 8; i++) {
        A0 = __fadd_rn(A0, __fmul_rn(x[4 * i + 0], x[4 * i + 0]));
        A1 = __fadd_rn(A1, __fmul_rn(x[4 * i + 1], x[4 * i + 1]));
        A2 = __fadd_rn(A2, __fmul_rn(x[4 * i + 2], x[4 * i + 2]));
        A3 = __fadd_rn(A3, __fmul_rn(x[4 * i + 3], x[4 * i + 3]));
    }
    return __fadd_rn(__fadd_rn(A0, A1), __fadd_rn(A2, A3));
}

__device__ __forceinline__ float sumsqdiff32(const float* q, const float* h) {
    float d0 = __fsub_rn(q[0], h[0]);
    float d1 = __fsub_rn(q[1], h[1]);
    float d2 = __fsub_rn(q[2], h[2]);
    float d3 = __fsub_rn(q[3], h[3]);
    float A0 = __fmul_rn(d0, d0);
    float A1 = __fmul_rn(d1, d1);
    float A2 = __fmul_rn(d2, d2);
    float A3 = __fmul_rn(d3, d3);
#pragma unroll
    for (int i = 1; i < 8; i++) {
        float e0 = __fsub_rn(q[4 * i + 0], h[4 * i + 0]);
        float e1 = __fsub_rn(q[4 * i + 1], h[4 * i + 1]);
        float e2 = __fsub_rn(q[4 * i + 2], h[4 * i + 2]);
        float e3 = __fsub_rn(q[4 * i + 3], h[4 * i + 3]);
        A0 = __fadd_rn(A0, __fmul_rn(e0, e0));
        A1 = __fadd_rn(A1, __fmul_rn(e1, e1));
        A2 = __fadd_rn(A2, __fmul_rn(e2, e2));
        A3 = __fadd_rn(A3, __fmul_rn(e3, e3));
    }
    return __fadd_rn(__fadd_rn(A0, A1), __fadd_rn(A2, A3));
}

extern __shared__ u64 g_sh[];

// Per-token finish: gather winning code from smem, loss, straight-through out.
// half selects which lane of hh holds this token's h.
__device__ __forceinline__ void finish_token(int tok, int bi, const u64* hh,
                                             int half, const u64* sE,
                                             float* __restrict__ out) {
    const int bp = bi >> 1, sel = bi & 1;
    float q[DIM], h[DIM];
#pragma unroll
    for (int k = 0; k < DIM; k++) {
        float lo, hi;
        upk2(sE[bp * DIM + k], lo, hi);
        q[k] = sel ? hi : lo;
        float hl, hr;
        upk2(hh[k], hl, hr);
        h[k] = half ? hr : hl;
    }
    float ssum = sumsqdiff32(q, h);
    float L    = __fmul_rn(ssum, 0.03125f);   // /32 exact
    float l1   = __fmul_rn(L, 0.1f);
    float loss = __fadd_rn(l1, l1);

    float4* oq = reinterpret_cast<float4*>(out + (size_t)tok * DIM);
#pragma unroll
    for (int v = 0; v < 8; v++) {
        float4 r;
        r.x = __fadd_rn(h[4 * v + 0], __fsub_rn(q[4 * v + 0], h[4 * v + 0]));
        r.y = __fadd_rn(h[4 * v + 1], __fsub_rn(q[4 * v + 1], h[4 * v + 1]));
        r.z = __fadd_rn(h[4 * v + 2], __fsub_rn(q[4 * v + 2], h[4 * v + 2]));
        r.w = __fadd_rn(h[4 * v + 3], __fsub_rn(q[4 * v + 3], h[4 * v + 3]));
        oq[v] = r;
    }
    out[(size_t)NTOK * DIM + tok] = (float)bi;
    out[(size_t)NTOK * DIM + NTOK + tok] = loss;
}

__global__ void __launch_bounds__(TPB, 1)
vq_kernel(const float* __restrict__ H, const float* __restrict__ E,
          float* __restrict__ out) {
    u64* sE = g_sh;                 // [NPAIR][DIM] : {e[2p][k], e[2p+1][k]}
    u64* sB = g_sh + NPAIR * DIM;   // [NPAIR]      : packed code norms

    const int tid = threadIdx.x;

    // ---- Embedding table -> pair-interleaved smem + norms ----
    for (int p = tid; p < NPAIR; p += TPB) {
        float e0[DIM], e1[DIM];
        const float4* r0 = reinterpret_cast<const float4*>(E + (size_t)(2 * p) * DIM);
        const float4* r1 = reinterpret_cast<const float4*>(E + (size_t)(2 * p + 1) * DIM);
#pragma unroll
        for (int v = 0; v < 8; v++) {
            float4 x = r0[v];
            e0[4 * v + 0] = x.x; e0[4 * v + 1] = x.y;
            e0[4 * v + 2] = x.z; e0[4 * v + 3] = x.w;
            float4 y = r1[v];
            e1[4 * v + 0] = y.x; e1[4 * v + 1] = y.y;
            e1[4 * v + 2] = y.z; e1[4 * v + 3] = y.w;
        }
#pragma unroll
        for (int k = 0; k < DIM; k++) sE[p * DIM + k] = pk2(e0[k], e1[k]);
        sB[p] = pk2(sumsq32(e0), sumsq32(e1));
    }

    // ---- Load 4 tokens as two token-pair packed register sets ----
    const int tok0 = blockIdx.x * (TPB * TPT) + tid * TPT;   // t0..t3 contiguous

    u64 hhA[DIM], hhB[DIM];
    float a0, a1, a2, a3;
    {
        const float4* p0 = reinterpret_cast<const float4*>(H + (size_t)tok0 * DIM);
        const float4* p1 = p0 + 8;
        float A0, A1, A2, A3, B0, B1, B2, B3;
        {
            float4 x = p0[0], y = p1[0];
            hhA[0] = pk2(x.x, y.x); hhA[1] = pk2(x.y, y.y);
            hhA[2] = pk2(x.z, y.z); hhA[3] = pk2(x.w, y.w);
            A0 = __fmul_rn(x.x, x.x); A1 = __fmul_rn(x.y, x.y);
            A2 = __fmul_rn(x.z, x.z); A3 = __fmul_rn(x.w, x.w);
            B0 = __fmul_rn(y.x, y.x); B1 = __fmul_rn(y.y, y.y);
            B2 = __fmul_rn(y.z, y.z); B3 = __fmul_rn(y.w, y.w);
        }
#pragma unroll
        for (int v = 1; v < 8; v++) {
            float4 x = p0[v], y = p1[v];
            hhA[4 * v + 0] = pk2(x.x, y.x); hhA[4 * v + 1] = pk2(x.y, y.y);
            hhA[4 * v + 2] = pk2(x.z, y.z); hhA[4 * v + 3] = pk2(x.w, y.w);
            A0 = __fadd_rn(A0, __fmul_rn(x.x, x.x));
            A1 = __fadd_rn(A1, __fmul_rn(x.y, x.y));
            A2 = __fadd_rn(A2, __fmul_rn(x.z, x.z));
            A3 = __fadd_rn(A3, __fmul_rn(x.w, x.w));
            B0 = __fadd_rn(B0, __fmul_rn(y.x, y.x));
            B1 = __fadd_rn(B1, __fmul_rn(y.y, y.y));
            B2 = __fadd_rn(B2, __fmul_rn(y.z, y.z));
            B3 = __fadd_rn(B3, __fmul_rn(y.w, y.w));
        }
        a0 = __fadd_rn(__fadd_rn(A0, A1), __fadd_rn(A2, A3));
        a1 = __fadd_rn(__fadd_rn(B0, B1), __fadd_rn(B2, B3));
    }
    {
        const float4* p2 = reinterpret_cast<const float4*>(H + (size_t)(tok0 + 2) * DIM);
        const float4* p3 = p2 + 8;
        float A0, A1, A2, A3, B0, B1, B2, B3;
        {
            float4 x = p2[0], y = p3[0];
            hhB[0] = pk2(x.x, y.x); hhB[1] = pk2(x.y, y.y);
            hhB[2] = pk2(x.z, y.z); hhB[3] = pk2(x.w, y.w);
            A0 = __fmul_rn(x.x, x.x); A1 = __fmul_rn(x.y, x.y);
            A2 = __fmul_rn(x.z, x.z); A3 = __fmul_rn(x.w, x.w);
            B0 = __fmul_rn(y.x, y.x); B1 = __fmul_rn(y.y, y.y);
            B2 = __fmul_rn(y.z, y.z); B3 = __fmul_rn(y.w, y.w);
        }
#pragma unroll
        for (int v = 1; v < 8; v++) {
            float4 x = p2[v], y = p3[v];
            hhB[4 * v + 0] = pk2(x.x, y.x); hhB[4 * v + 1] = pk2(x.y, y.y);
            hhB[4 * v + 2] = pk2(x.z, y.z); hhB[4 * v + 3] = pk2(x.w, y.w);
            A0 = __fadd_rn(A0, __fmul_rn(x.x, x.x));
            A1 = __fadd_rn(A1, __fmul_rn(x.y, x.y));
            A2 = __fadd_rn(A2, __fmul_rn(x.z, x.z));
            A3 = __fadd_rn(A3, __fmul_rn(x.w, x.w));
            B0 = __fadd_rn(B0, __fmul_rn(y.x, y.x));
            B1 = __fadd_rn(B1, __fmul_rn(y.y, y.y));
            B2 = __fadd_rn(B2, __fmul_rn(y.z, y.z));
            B3 = __fadd_rn(B3, __fmul_rn(y.w, y.w));
        }
        a2 = __fadd_rn(__fadd_rn(A0, A1), __fadd_rn(A2, A3));
        a3 = __fadd_rn(__fadd_rn(B0, B1), __fadd_rn(B2, B3));
    }

    const u64 aA   = pk2(a0, a1);
    const u64 aB   = pk2(a2, a3);
    const u64 neg2 = pk2(-2.0f, -2.0f);
    const u64 zz   = pk2(0.0f, 0.0f);

    __syncthreads();

    // ---- Main loop: 2 code-pairs (4 codes) x 4 tokens per tile ----
    const float INFP = __int_as_float(0x7f800000);
    float bb0 = INFP, bb1 = INFP, bb2 = INFP, bb3 = INFP;
    int bi0 = 0, bi1 = 0, bi2 = 0, bi3 = 0;

#pragma unroll 1
    for (int p0 = 0; p0 < NPAIR; p0 += 2) {
        // acc lanes: o* = (t_even . c_even, t_odd . c_odd)
        //            s* = (t_even . c_odd,  t_odd . c_even)
        u64 oA0 = zz, sA0 = zz, oB0 = zz, sB0 = zz;   // pair p0
        u64 oA1 = zz, sA1 = zz, oB1 = zz, sB1 = zz;   // pair p0+1
#pragma unroll
        for (int k = 0; k < DIM; k += 2) {
            ulonglong2 v0 = *reinterpret_cast<const ulonglong2*>(&sE[(p0 + 0) * DIM + k]);
            ulonglong2 v1 = *reinterpret_cast<const ulonglong2*>(&sE[(p0 + 1) * DIM + k]);
            u64 w0 = swp2(v0.x), w1 = swp2(v1.x);
            oA0 = ffma2(v0.x, hhA[k], oA0);
            sA0 = ffma2(w0,   hhA[k], sA0);
            oB0 = ffma2(v0.x, hhB[k], oB0);
            sB0 = ffma2(w0,   hhB[k], sB0);
            oA1 = ffma2(v1.x, hhA[k], oA1);
            sA1 = ffma2(w1,   hhA[k], sA1);
            oB1 = ffma2(v1.x, hhB[k], oB1);
            sB1 = ffma2(w1,   hhB[k], sB1);
            u64 u0 = swp2(v0.y), u1 = swp2(v1.y);
            oA0 = ffma2(v0.y, hhA[k + 1], oA0);
            sA0 = ffma2(u0,   hhA[k + 1], sA0);
            oB0 = ffma2(v0.y, hhB[k + 1], oB0);
            sB0 = ffma2(u0,   hhB[k + 1], sB0);
            oA1 = ffma2(v1.y, hhA[k + 1], oA1);
            sA1 = ffma2(u1,   hhA[k + 1], sA1);
            oB1 = ffma2(v1.y, hhB[k + 1], oB1);
            sB1 = ffma2(u1,   hhB[k + 1], sB1);
        }
        // dist + argmin, pairs in ascending code order (tie = first index)
        u64 accO_A[2] = {oA0, oA1}, accS_A[2] = {sA0, sA1};
        u64 accO_B[2] = {oB0, oB1}, accS_B[2] = {sB0, sB1};
#pragma unroll
        for (int u = 0; u < 2; u++) {
            const int p = p0 + u;
            u64 nb  = sB[p];
            u64 nbs = swp2(nb);
            u64 dOA = ffma2(accO_A[u], neg2, fadd2(aA, nb));   // (d(t0,c0), d(t1,c1))
            u64 dSA = ffma2(accS_A[u], neg2, fadd2(aA, nbs));  // (d(t0,c1), d(t1,c0))
            u64 dOB = ffma2(accO_B[u], neg2, fadd2(aB, nb));   // (d(t2,c0), d(t3,c1))
            u64 dSB = ffma2(accS_B[u], neg2, fadd2(aB, nbs));  // (d(t2,c1), d(t3,c0))
            float x0, x1, y0, y1, z0, z1, w0f, w1f;
            upk2(dOA, x0, x1);
            upk2(dSA, y0, y1);
            upk2(dOB, z0, z1);
            upk2(dSB, w0f, w1f);
            const int j0 = 2 * p, j1 = 2 * p + 1;
            if (x0  < bb0) { bb0 = x0;  bi0 = j0; }
            if (y0  < bb0) { bb0 = y0;  bi0 = j1; }
            if (y1  < bb1) { bb1 = y1;  bi1 = j0; }
            if (x1  < bb1) { bb1 = x1;  bi1 = j1; }
            if (z0  < bb2) { bb2 = z0;  bi2 = j0; }
            if (w0f < bb2) { bb2 = w0f; bi2 = j1; }
            if (w1f < bb3) { bb3 = w1f; bi3 = j0; }
            if (z1  < bb3) { bb3 = z1;  bi3 = j1; }
        }
    }

    // ---- Finish all 4 tokens ----
    finish_token(tok0 + 0, bi0, hhA, 0, sE, out);
    finish_token(tok0 + 1, bi1, hhA, 1, sE, out);
    finish_token(tok0 + 2, bi2, hhB, 0, sE, out);
    finish_token(tok0 + 3, bi3, hhB, 1, sE, out);
}

extern "C" void kernel_launch(void* const* d_in, const int* in_sizes, int n_in,
                              void* d_out, int out_size) {
    (void)in_sizes; (void)n_in; (void)out_size;
    const float* H = (const float*)d_in[0];
    const float* E = (const float*)d_in[1];
    size_t smem = (size_t)(NPAIR * DIM + NPAIR) * sizeof(u64);  // 135168 B
    cudaFuncSetAttribute(vq_kernel, cudaFuncAttributeMaxDynamicSharedMemorySize,
                         (int)smem);
    vq_kernel<<<NBLK, TPB, smem>>>(H, E, (float*)d_out);
}

// round 9
// speedup vs baseline: 1.0287x; 1.0287x over previous
#include <cuda_runtime.h>

// VQ-VAE quantizer, round 9: f32x2 FFMA2 path (tcgen05 unavailable: harness
// builds via compute_103 virtual arch which rejects sm_103a-only PTX).
//   h: (256,512,32) f32 -> 131072 tokens x 32;  embeddings: (1024,32) f32
//   out f32: qst (131072*32) | indices (131072) | loss (131072)
//
// vs R6 (221.6us, fma 51.6%, issue 41.9%, grid 128):
//  - grid 148 (all SMs busy): 886 tokens/block, 222 active threads x TPT=4,
//    edge tokens clamped to NTOK-1 (duplicate writes are bit-identical).
//  - e-loads software-pipelined 2 k-steps ahead (rotating register stages)
//    to hide the 29-cyc LDS latency.
// Arithmetic identical to the verified R5/R6 fp32 expression tree.

#define DIM    32
#define NCODES 1024
#define NPAIR  (NCODES / 2)   // 512
#define TPB    256
#define NTOK   131072
#define TPT    4
#define NBLK   148
#define TOKPB  886            // ceil(131072/148); 148*886 = 131128 >= NTOK

typedef unsigned long long u64;

__device__ __forceinline__ u64 pk2(float lo, float hi) {
    u64 r;
    asm("mov.b64 %0, {%1, %2};" : "=l"(r) : "f"(lo), "f"(hi));
    return r;
}
__device__ __forceinline__ void upk2(u64 v, float& lo, float& hi) {
    asm("mov.b64 {%0, %1}, %2;" : "=f"(lo), "=f"(hi) : "l"(v));
}
__device__ __forceinline__ u64 swp2(u64 v) {
    float lo, hi;
    upk2(v, lo, hi);
    return pk2(hi, lo);
}
__device__ __forceinline__ u64 ffma2(u64 a, u64 b, u64 c) {
    u64 d;
    asm("fma.rn.f32x2 %0, %1, %2, %3;" : "=l"(d) : "l"(a), "l"(b), "l"(c));
    return d;
}
__device__ __forceinline__ u64 fadd2(u64 a, u64 b) {
    u64 d;
    asm("add.rn.f32x2 %0, %1, %2;" : "=l"(d) : "l"(a), "l"(b));
    return d;
}

// ||x||^2, reference-order reduction (verified bit-exact R5).
__device__ __forceinline__ float sumsq32(const float* x) {
    float A0 = __fmul_rn(x[0], x[0]), A1 = __fmul_rn(x[1], x[1]);
    float A2 = __fmul_rn(x[2], x[2]), A3 = __fmul_rn(x[3], x[3]);
#pragma unroll
    for (int i = 1; i < 8; i++) {
        A0 = __fadd_rn(A0, __fmul_rn(x[4*i+0], x[4*i+0]));
        A1 = __fadd_rn(A1, __fmul_rn(x[4*i+1], x[4*i+1]));
        A2 = __fadd_rn(A2, __fmul_rn(x[4*i+2], x[4*i+2]));
        A3 = __fadd_rn(A3, __fmul_rn(x[4*i+3], x[4*i+3]));
    }
    return __fadd_rn(__fadd_rn(A0, A1), __fadd_rn(A2, A3));
}
__device__ __forceinline__ float sumsqdiff32(const float* q, const float* h) {
    float A0, A1, A2, A3;
    {
        float d0 = __fsub_rn(q[0], h[0]), d1 = __fsub_rn(q[1], h[1]);
        float d2 = __fsub_rn(q[2], h[2]), d3 = __fsub_rn(q[3], h[3]);
        A0 = __fmul_rn(d0, d0); A1 = __fmul_rn(d1, d1);
        A2 = __fmul_rn(d2, d2); A3 = __fmul_rn(d3, d3);
    }
#pragma unroll
    for (int i = 1; i < 8; i++) {
        float e0 = __fsub_rn(q[4*i+0], h[4*i+0]), e1 = __fsub_rn(q[4*i+1], h[4*i+1]);
        float e2 = __fsub_rn(q[4*i+2], h[4*i+2]), e3 = __fsub_rn(q[4*i+3], h[4*i+3]);
        A0 = __fadd_rn(A0, __fmul_rn(e0, e0));
        A1 = __fadd_rn(A1, __fmul_rn(e1, e1));
        A2 = __fadd_rn(A2, __fmul_rn(e2, e2));
        A3 = __fadd_rn(A3, __fmul_rn(e3, e3));
    }
    return __fadd_rn(__fadd_rn(A0, A1), __fadd_rn(A2, A3));
}

extern __shared__ u64 g_sh[];

__device__ __forceinline__ void finish_token(int tok, int bi, const u64* hh,
                                             int half, const u64* sE,
                                             float* __restrict__ out) {
    const int bp = bi >> 1, sel = bi & 1;
    float q[DIM], h[DIM];
#pragma unroll
    for (int k = 0; k < DIM; k++) {
        float lo, hi;
        upk2(sE[bp * DIM + k], lo, hi);
        q[k] = sel ? hi : lo;
        float hl, hr;
        upk2(hh[k], hl, hr);
        h[k] = half ? hr : hl;
    }
    float ssum = sumsqdiff32(q, h);
    float L    = __fmul_rn(ssum, 0.03125f);
    float l1   = __fmul_rn(L, 0.1f);
    float loss = __fadd_rn(l1, l1);

    float4* oq = reinterpret_cast<float4*>(out + (size_t)tok * DIM);
#pragma unroll
    for (int v = 0; v < 8; v++) {
        float4 r;
        r.x = __fadd_rn(h[4*v+0], __fsub_rn(q[4*v+0], h[4*v+0]));
        r.y = __fadd_rn(h[4*v+1], __fsub_rn(q[4*v+1], h[4*v+1]));
        r.z = __fadd_rn(h[4*v+2], __fsub_rn(q[4*v+2], h[4*v+2]));
        r.w = __fadd_rn(h[4*v+3], __fsub_rn(q[4*v+3], h[4*v+3]));
        oq[v] = r;
    }
    out[(size_t)NTOK * DIM + tok] = (float)bi;
    out[(size_t)NTOK * DIM + NTOK + tok] = loss;
}

// Load one token's h (32 f32) with clamped index.
__device__ __forceinline__ void load_h(const float* __restrict__ H, int tok,
                                       float* h) {
    const float4* p = reinterpret_cast<const float4*>(H + (size_t)tok * DIM);
#pragma unroll
    for (int v = 0; v < 8; v++) {
        float4 x = p[v];
        h[4*v+0] = x.x; h[4*v+1] = x.y; h[4*v+2] = x.z; h[4*v+3] = x.w;
    }
}

__global__ void __launch_bounds__(TPB, 1)
vq_kernel(const float* __restrict__ H, const float* __restrict__ E,
          float* __restrict__ out) {
    u64* sE = g_sh;                 // [NPAIR][DIM] pair-interleaved e
    u64* sB = g_sh + NPAIR * DIM;   // [NPAIR] packed code norms

    const int tid = threadIdx.x;

    // ---- Embedding table -> smem (all 256 threads) ----
#pragma unroll
    for (int pp = 0; pp < 2; pp++) {
        const int p = tid + pp * TPB;
        float e0[DIM], e1[DIM];
        const float4* r0 = reinterpret_cast<const float4*>(E + (size_t)(2*p) * DIM);
        const float4* r1 = reinterpret_cast<const float4*>(E + (size_t)(2*p+1) * DIM);
#pragma unroll
        for (int v = 0; v < 8; v++) {
            float4 x = r0[v];
            e0[4*v+0] = x.x; e0[4*v+1] = x.y; e0[4*v+2] = x.z; e0[4*v+3] = x.w;
            float4 y = r1[v];
            e1[4*v+0] = y.x; e1[4*v+1] = y.y; e1[4*v+2] = y.z; e1[4*v+3] = y.w;
        }
#pragma unroll
        for (int k = 0; k < DIM; k++) sE[p * DIM + k] = pk2(e0[k], e1[k]);
        sB[p] = pk2(sumsq32(e0), sumsq32(e1));
    }
    __syncthreads();

    // ---- 222 active threads x 4 tokens; others done ----
    if (tid >= 222) return;

    const int base = blockIdx.x * TOKPB;
    int tk0 = base + tid * TPT;
    int tk1 = tk0 + 1, tk2 = tk0 + 2, tk3 = tk0 + 3;
    if (tk0 > NTOK - 1) tk0 = NTOK - 1;
    if (tk1 > NTOK - 1) tk1 = NTOK - 1;
    if (tk2 > NTOK - 1) tk2 = NTOK - 1;
    if (tk3 > NTOK - 1) tk3 = NTOK - 1;

    u64 hhA[DIM], hhB[DIM];
    float a0, a1, a2, a3;
    {
        float x[DIM], y[DIM];
        load_h(H, tk0, x);
        load_h(H, tk1, y);
#pragma unroll
        for (int k = 0; k < DIM; k++) hhA[k] = pk2(x[k], y[k]);
        a0 = sumsq32(x); a1 = sumsq32(y);
        load_h(H, tk2, x);
        load_h(H, tk3, y);
#pragma unroll
        for (int k = 0; k < DIM; k++) hhB[k] = pk2(x[k], y[k]);
        a2 = sumsq32(x); a3 = sumsq32(y);
    }

    const u64 aA   = pk2(a0, a1);
    const u64 aB   = pk2(a2, a3);
    const u64 neg2 = pk2(-2.0f, -2.0f);
    const u64 zz   = pk2(0.0f, 0.0f);

    const float INFP = __int_as_float(0x7f800000);
    float bb0 = INFP, bb1 = INFP, bb2 = INFP, bb3 = INFP;
    int bi0 = 0, bi1 = 0, bi2 = 0, bi3 = 0;

    // ---- Main loop: tile = 2 code-pairs x 4 tokens, e-loads pipelined ----
#pragma unroll 1
    for (int p0 = 0; p0 < NPAIR; p0 += 2) {
        u64 oA0 = zz, sA0 = zz, oB0 = zz, sB0 = zz;
        u64 oA1 = zz, sA1 = zz, oB1 = zz, sB1 = zz;

        const ulonglong2* e0p = reinterpret_cast<const ulonglong2*>(&sE[(p0 + 0) * DIM]);
        const ulonglong2* e1p = reinterpret_cast<const ulonglong2*>(&sE[(p0 + 1) * DIM]);

        // 2-deep rotating prefetch stages (full unroll -> registers)
        ulonglong2 st0[2], st1[2];
        st0[0] = e0p[0]; st1[0] = e1p[0];
        st0[1] = e0p[1]; st1[1] = e1p[1];

#pragma unroll
        for (int j = 0; j < 16; j++) {          // k = 2*j
            ulonglong2 v0 = st0[j & 1];
            ulonglong2 v1 = st1[j & 1];
            if (j < 14) {                        // prefetch k-step j+2
                st0[j & 1] = e0p[j + 2];
                st1[j & 1] = e1p[j + 2];
            }
            const int k = 2 * j;
            u64 w0 = swp2(v0.x), w1 = swp2(v1.x);
            oA0 = ffma2(v0.x, hhA[k], oA0);
            sA0 = ffma2(w0,   hhA[k], sA0);
            oB0 = ffma2(v0.x, hhB[k], oB0);
            sB0 = ffma2(w0,   hhB[k], sB0);
            oA1 = ffma2(v1.x, hhA[k], oA1);
            sA1 = ffma2(w1,   hhA[k], sA1);
            oB1 = ffma2(v1.x, hhB[k], oB1);
            sB1 = ffma2(w1,   hhB[k], sB1);
            u64 u0 = swp2(v0.y), u1 = swp2(v1.y);
            oA0 = ffma2(v0.y, hhA[k + 1], oA0);
            sA0 = ffma2(u0,   hhA[k + 1], sA0);
            oB0 = ffma2(v0.y, hhB[k + 1], oB0);
            sB0 = ffma2(u0,   hhB[k + 1], sB0);
            oA1 = ffma2(v1.y, hhA[k + 1], oA1);
            sA1 = ffma2(u1,   hhA[k + 1], sA1);
            oB1 = ffma2(v1.y, hhB[k + 1], oB1);
            sB1 = ffma2(u1,   hhB[k + 1], sB1);
        }

        u64 accO_A[2] = {oA0, oA1}, accS_A[2] = {sA0, sA1};
        u64 accO_B[2] = {oB0, oB1}, accS_B[2] = {sB0, sB1};
#pragma unroll
        for (int u = 0; u < 2; u++) {
            const int p = p0 + u;
            u64 nb  = sB[p];
            u64 nbs = swp2(nb);
            u64 dOA = ffma2(accO_A[u], neg2, fadd2(aA, nb));
            u64 dSA = ffma2(accS_A[u], neg2, fadd2(aA, nbs));
            u64 dOB = ffma2(accO_B[u], neg2, fadd2(aB, nb));
            u64 dSB = ffma2(accS_B[u], neg2, fadd2(aB, nbs));
            float x0, x1, y0, y1, z0, z1, w0f, w1f;
            upk2(dOA, x0, x1);
            upk2(dSA, y0, y1);
            upk2(dOB, z0, z1);
            upk2(dSB, w0f, w1f);
            const int j0 = 2 * p, j1 = 2 * p + 1;
            if (x0  < bb0) { bb0 = x0;  bi0 = j0; }
            if (y0  < bb0) { bb0 = y0;  bi0 = j1; }
            if (y1  < bb1) { bb1 = y1;  bi1 = j0; }
            if (x1  < bb1) { bb1 = x1;  bi1 = j1; }
            if (z0  < bb2) { bb2 = z0;  bi2 = j0; }
            if (w0f < bb2) { bb2 = w0f; bi2 = j1; }
            if (w1f < bb3) { bb3 = w1f; bi3 = j0; }
            if (z1  < bb3) { bb3 = z1;  bi3 = j1; }
        }
    }

    finish_token(tk0, bi0, hhA, 0, sE, out);
    finish_token(tk1, bi1, hhA, 1, sE, out);
    finish_token(tk2, bi2, hhB, 0, sE, out);
    finish_token(tk3, bi3, hhB, 1, sE, out);
}

extern "C" void kernel_launch(void* const* d_in, const int* in_sizes, int n_in,
                              void* d_out, int out_size) {
    (void)in_sizes; (void)n_in; (void)out_size;
    const float* H = (const float*)d_in[0];
    const float* E = (const float*)d_in[1];
    size_t smem = (size_t)(NPAIR * DIM + NPAIR) * sizeof(u64);  // 135168 B
    cudaFuncSetAttribute(vq_kernel, cudaFuncAttributeMaxDynamicSharedMemorySize,
                         (int)smem);
    vq_kernel<<<NBLK, TPB, smem>>>(H, E, (float*)d_out);
}